// round 9
// baseline (speedup 1.0000x reference)
#include <cuda_runtime.h>
#include <cuda_bf16.h>
#include <math.h>
#include <stdint.h>

#define BQ   16
#define TT   1000
#define MEL  80
#define HID  512
#define NCLS 64
#define NROW (BQ*TT)

#define CLN  8       // CTAs per cluster (8 clusters x 8 CTAs = 64: proven placement)
#define NCTA 64
#define BPC  2       // batch elements per cluster

#define WROWB 1040u                 // bf16 row stride bytes (1024 + 16 pad)
#define WMATB (64u*WROWB)
#define DYNSM (2u*WMATB)            // 133120 B

#define TXE (4096u + 64u)           // err exchange: 8 CTAs*512B + 8*8B norm
#define TXH 4096u                   // h exchange

// ---------------- scratch (static device globals; no allocations) ----------------
__device__ float g_be0[NROW*HID];
__device__ float g_be1[NROW*HID];
__device__ float g_h1 [NROW*HID];
__device__ float g_xs1[NROW];

__device__ __forceinline__ float sigm(float x){ return 1.0f/(1.0f+expf(-x)); }

__device__ __forceinline__ uint32_t smem_u32(const void* p){
  uint32_t a;
  asm("{ .reg .u64 t; cvta.to.shared.u64 t, %1; cvt.u32.u64 %0, t; }" : "=r"(a) : "l"(p));
  return a;
}
__device__ __forceinline__ uint32_t mapa32(uint32_t laddr, uint32_t rnk){
  uint32_t ra;
  asm("mapa.shared::cluster.u32 %0, %1, %2;" : "=r"(ra) : "r"(laddr), "r"(rnk));
  return ra;
}
__device__ __forceinline__ void stasync_v4(uint32_t raddr, uint32_t rbar, uint4 v){
  asm volatile("st.async.shared::cluster.mbarrier::complete_tx::bytes.v4.b32 "
               "[%0], {%1,%2,%3,%4}, [%5];"
               :: "r"(raddr), "r"(v.x), "r"(v.y), "r"(v.z), "r"(v.w), "r"(rbar)
               : "memory");
}
__device__ __forceinline__ void stasync_v2(uint32_t raddr, uint32_t rbar, float a, float b){
  asm volatile("st.async.shared::cluster.mbarrier::complete_tx::bytes.v2.b32 "
               "[%0], {%1,%2}, [%3];"
               :: "r"(raddr), "r"(__float_as_uint(a)), "r"(__float_as_uint(b)), "r"(rbar)
               : "memory");
}
__device__ __forceinline__ void mbar_init(uint32_t addr, uint32_t cnt){
  asm volatile("mbarrier.init.shared.b64 [%0], %1;" :: "r"(addr), "r"(cnt) : "memory");
}
__device__ __forceinline__ void mbar_expect(uint32_t addr, uint32_t tx){
  asm volatile("mbarrier.arrive.expect_tx.shared.b64 _, [%0], %1;"
               :: "r"(addr), "r"(tx) : "memory");
}
__device__ __forceinline__ void mbar_wait(uint32_t addr, uint32_t parity){
  uint32_t done;
  asm volatile(
    "{\n\t.reg .pred p;\n\t"
    "mbarrier.try_wait.parity.acquire.cta.shared::cta.b64 p, [%1], %2;\n\t"
    "selp.b32 %0, 1, 0, p;\n\t}"
    : "=r"(done) : "r"(addr), "r"(parity) : "memory");
  if (!done){
    asm volatile(
      "{\n\t.reg .pred P1;\n\t"
      "WL_%=:\n\t"
      "mbarrier.try_wait.parity.acquire.cta.shared::cta.b64 P1, [%0], %1, 0x989680;\n\t"
      "@P1 bra.uni WD_%=;\n\t"
      "bra.uni WL_%=;\n\t"
      "WD_%=:\n\t}"
      :: "r"(addr), "r"(parity) : "memory");
  }
}
#define CLUSTER_SYNC() do{ \
  asm volatile("barrier.cluster.arrive.aligned;" ::: "memory"); \
  asm volatile("barrier.cluster.wait.aligned;"  ::: "memory"); }while(0)

// packed f32x2 helpers
__device__ __forceinline__ unsigned long long bpack(unsigned lo, unsigned hi){
  unsigned long long r;
  asm("mov.b64 %0, {%1,%2};" : "=l"(r) : "r"(lo), "r"(hi));
  return r;
}
__device__ __forceinline__ void ffma2(unsigned long long& a, unsigned long long w,
                                      unsigned long long x){
  asm("fma.rn.f32x2 %0, %1, %2, %0;" : "+l"(a) : "l"(w), "l"(x));
}
__device__ __forceinline__ float hsum2(unsigned long long a){
  return __uint_as_float((unsigned)(a & 0xffffffffu)) +
         __uint_as_float((unsigned)(a >> 32));
}

// ---------------- be0 = clip(feats/||feats||) @ B0^T ; xs1 = ||be0|| ----------------
__global__ __launch_bounds__(256) void k_be0(const float* __restrict__ feats,
                                             const float* __restrict__ B0){
  __shared__ float xn[16][MEL];
  __shared__ float snorm[16];
  __shared__ float sxs[16];
  int tid = threadIdx.x;
  int row0 = blockIdx.x*16;
  for (int i=tid;i<16*MEL;i+=256)
    xn[i/MEL][i%MEL] = feats[row0*MEL + i];
  __syncthreads();
  if (tid<16){
    float s=0.f;
    #pragma unroll
    for (int k=0;k<MEL;k++){ float v=xn[tid][k]; s+=v*v; }
    sxs[tid]=fmaxf(sqrtf(s),1e-6f);
    snorm[tid]=0.f;
  }
  __syncthreads();
  for (int i=tid;i<16*MEL;i+=256){
    int r=i/MEL;
    float v = xn[r][i%MEL]/sxs[r];
    xn[r][i%MEL] = fminf(fmaxf(v,-1.f),1.f);
  }
  __syncthreads();
  int n0=tid, n1=tid+256;
  float a0[16], a1_[16];
  #pragma unroll
  for (int r=0;r<16;r++){ a0[r]=0.f; a1_[r]=0.f; }
  for (int k=0;k<MEL;k+=4){
    float4 w0 = *(const float4*)&B0[n0*MEL+k];
    float4 w1 = *(const float4*)&B0[n1*MEL+k];
    #pragma unroll
    for (int r=0;r<16;r++){
      float4 x = *(const float4*)&xn[r][k];
      a0 [r] += w0.x*x.x + w0.y*x.y + w0.z*x.z + w0.w*x.w;
      a1_[r] += w1.x*x.x + w1.y*x.y + w1.z*x.z + w1.w*x.w;
    }
  }
  #pragma unroll
  for (int r=0;r<16;r++){
    g_be0[(row0+r)*HID+n0]=a0[r];
    g_be0[(row0+r)*HID+n1]=a1_[r];
    atomicAdd(&snorm[r], a0[r]*a0[r] + a1_[r]*a1_[r]);
  }
  __syncthreads();
  if (tid<16) g_xs1[row0+tid] = fmaxf(sqrtf(snorm[tid]),1e-6f);
}

// ---------------- be1 = clip(be0/xs1) @ B1^T ----------------
__global__ __launch_bounds__(256) void k_be1(const float* __restrict__ B1){
  __shared__ float xn[16][HID];
  __shared__ float sxs[16];
  int tid=threadIdx.x;
  int row0=blockIdx.x*16;
  if (tid<16) sxs[tid]=g_xs1[row0+tid];
  __syncthreads();
  for (int i=tid;i<16*HID;i+=256){
    int r=i>>9;
    float v = g_be0[row0*HID + i]/sxs[r];
    xn[r][i&511] = fminf(fmaxf(v,-1.f),1.f);
  }
  __syncthreads();
  int n0=tid, n1=tid+256;
  float a0[16], a1_[16];
  #pragma unroll
  for (int r=0;r<16;r++){ a0[r]=0.f; a1_[r]=0.f; }
  for (int k=0;k<HID;k+=4){
    float4 w0 = *(const float4*)&B1[n0*HID+k];
    float4 w1 = *(const float4*)&B1[n1*HID+k];
    #pragma unroll
    for (int r=0;r<16;r++){
      float4 x = *(const float4*)&xn[r][k];
      a0 [r] += w0.x*x.x + w0.y*x.y + w0.z*x.z + w0.w*x.w;
      a1_[r] += w1.x*x.x + w1.y*x.y + w1.z*x.z + w1.w*x.w;
    }
  }
  #pragma unroll
  for (int r=0;r<16;r++){
    g_be1[(row0+r)*HID+n0]=a0[r];
    g_be1[(row0+r)*HID+n1]=a1_[r];
  }
}

// ---------------- serial recurrence: st.async + mbarrier exchange -----------------
// CTA `rank` owns rows [rank*64,+64). Weights bf16 in smem, (row,kq) map with
// x broadcast; dots via fma.rn.f32x2. Slices exchanged by st.async with
// mbarrier complete_tx; no cluster barriers in the loop.
__device__ __forceinline__ void dotp(const uint8_t* __restrict__ wsm,
                                     const float* __restrict__ xP,  // [2*512] planar
                                     int row, int kq,
                                     float& outA, float& outB){
  const uint8_t* wr = wsm + (unsigned)row*WROWB + (unsigned)kq*16u;
  unsigned long long aA0=0, aA1=0, aB0=0, aB1=0;
  #pragma unroll
  for (int m=0;m<16;m++){
    uint4 w = *(const uint4*)(wr + (unsigned)m*64u);
    int q = (kq + m*4)*8;
    ulonglong2 x0 = *(const ulonglong2*)(xP + q);
    ulonglong2 x1 = *(const ulonglong2*)(xP + q + 4);
    ulonglong2 y0 = *(const ulonglong2*)(xP + 512 + q);
    ulonglong2 y1 = *(const ulonglong2*)(xP + 512 + q + 4);
    unsigned long long p0 = bpack(w.x<<16, w.x&0xffff0000u);
    unsigned long long p1 = bpack(w.y<<16, w.y&0xffff0000u);
    unsigned long long p2 = bpack(w.z<<16, w.z&0xffff0000u);
    unsigned long long p3 = bpack(w.w<<16, w.w&0xffff0000u);
    if (m&1){
      ffma2(aA1,p0,x0.x); ffma2(aA1,p1,x0.y); ffma2(aA1,p2,x1.x); ffma2(aA1,p3,x1.y);
      ffma2(aB1,p0,y0.x); ffma2(aB1,p1,y0.y); ffma2(aB1,p2,y1.x); ffma2(aB1,p3,y1.y);
    } else {
      ffma2(aA0,p0,x0.x); ffma2(aA0,p1,x0.y); ffma2(aA0,p2,x1.x); ffma2(aA0,p3,x1.y);
      ffma2(aB0,p0,y0.x); ffma2(aB0,p1,y0.y); ffma2(aB0,p2,y1.x); ffma2(aB0,p3,y1.y);
    }
  }
  outA = hsum2(aA0)+hsum2(aA1);
  outB = hsum2(aB0)+hsum2(aB1);
}

__global__ __launch_bounds__(256,1) __cluster_dims__(CLN,1,1)
void k_serial(const float* __restrict__ C1, const float* __restrict__ W1,
              const float* __restrict__ a1, const float* __restrict__ tau,
              const float* __restrict__ gam){
  extern __shared__ __align__(16) uint8_t dynsm[];
  uint8_t* wsmC = dynsm;                 // [64][WROWB] bf16
  uint8_t* wsmW = dynsm + WMATB;

  __shared__ __align__(16) float hbufP[BPC*HID];   // planar h   (remote-written)
  __shared__ __align__(16) float ebufP[BPC*HID];   // planar err (remote-written)
  __shared__ __align__(16) float estageP[BPC*64];
  __shared__ __align__(16) float hstageP[BPC*64];
  __shared__ float2 pout2[64];
  __shared__ __align__(8) float2 narr2[CLN];       // (norm_b0, norm_b1) per src
  __shared__ float normloc[BPC];
  __shared__ float sa[64];
  __shared__ __align__(8) unsigned long long mbarE, mbarH;

  const int tid  = threadIdx.x;
  const int rank = blockIdx.x & (CLN-1);
  const int b0   = (blockIdx.x / CLN) * BPC;
  const int row  = tid >> 2, kq = tid & 3;
  const float tauv = __ldg(&tau[0]), gamv = __ldg(&gam[0]);

  // -------- prologue: convert weight slices fp32 -> bf16 smem --------
  for (int i=tid; i<64*128; i+=256){
    int r=i>>7, q=i&127;
    float4 vc = __ldg((const float4*)&C1[(rank*64+r)*HID + q*4]);
    float4 vw = __ldg((const float4*)&W1[(rank*64+r)*HID + q*4]);
    __nv_bfloat162 c0 = __floats2bfloat162_rn(vc.x, vc.y);
    __nv_bfloat162 c1 = __floats2bfloat162_rn(vc.z, vc.w);
    __nv_bfloat162 w0 = __floats2bfloat162_rn(vw.x, vw.y);
    __nv_bfloat162 w1 = __floats2bfloat162_rn(vw.z, vw.w);
    uint2 uc; uc.x = *(uint32_t*)&c0; uc.y = *(uint32_t*)&c1;
    uint2 uw; uw.x = *(uint32_t*)&w0; uw.y = *(uint32_t*)&w1;
    *(uint2*)(wsmC + (unsigned)r*WROWB + (unsigned)q*8u) = uc;
    *(uint2*)(wsmW + (unsigned)r*WROWB + (unsigned)q*8u) = uw;
  }
  for (int i=tid;i<BPC*HID;i+=256) hbufP[i]=0.f;
  if (tid<BPC) normloc[tid]=0.f;
  if (tid<64)  sa[tid] = sigm(__ldg(&a1[rank*64+tid]));
  if (tid==0){
    mbar_init(smem_u32(&mbarE), 1);
    mbar_init(smem_u32(&mbarH), 1);
  }
  __syncthreads();
  CLUSTER_SYNC();                       // mbarrier init visible cluster-wide

  const uint32_t abE = smem_u32(&mbarE), abH = smem_u32(&mbarH);
  // push mapping: warp w -> dest CTA w; lane = 1 float4 of the 512B slice
  const uint32_t dest = tid >> 5, lane = tid & 31;
  const uint32_t pb = lane >> 4, li = lane & 15;
  const uint32_t doff = (pb*512u + (unsigned)rank*64u + li*4u)*4u;
  const uint32_t raE  = mapa32(smem_u32(ebufP) + doff, dest);
  const uint32_t raH  = mapa32(smem_u32(hbufP) + doff, dest);
  const uint32_t rbE  = mapa32(abE, dest);
  const uint32_t rbH  = mapa32(abH, dest);
  uint32_t raN=0, rbN=0;
  if (tid<8){
    raN = mapa32(smem_u32(narr2) + (unsigned)rank*8u, (uint32_t)tid);
    rbN = mapa32(abE, (uint32_t)tid);
  }
  const int eb = tid & 1, erow = tid >> 1;            // epilogue mapping (tid<128)

  for (int t=0;t<TT;t++){
    const uint32_t par = (uint32_t)(t & 1);
    // prefetch per-step scalars
    float xsv=1.f, be0v=0.f, be1v=0.f;
    if (tid<128){
      int bb = b0+eb;
      xsv  = __ldg(&g_xs1[bb*TT+t]);
      be0v = __ldg(&g_be0[(bb*TT+t)*HID + rank*64 + erow]);
      be1v = __ldg(&g_be1[(bb*TT+t)*HID + rank*64 + erow]);
    }

    // ======== phase 1: p = h @ C1^T, err, norm ========
    {
      float sA, sB;
      dotp(wsmC, hbufP, row, kq, sA, sB);
      sA += __shfl_down_sync(0xffffffffu, sA, 2, 4);
      sA += __shfl_down_sync(0xffffffffu, sA, 1, 4);
      sB += __shfl_down_sync(0xffffffffu, sB, 2, 4);
      sB += __shfl_down_sync(0xffffffffu, sB, 1, 4);
      if (kq==0) pout2[row] = make_float2(sA, sB);
    }
    __syncthreads();
    if (tid<128){
      float pv = eb ? pout2[erow].y : pout2[erow].x;
      float e = be0v - tanhf(pv)*xsv;
      estageP[eb*64+erow] = e;
      float q = e*e;
      #pragma unroll
      for (int off=16; off>=2; off>>=1) q += __shfl_xor_sync(0xffffffffu,q,off);
      if ((tid&31)<2) atomicAdd(&normloc[tid&1], q);
    }
    __syncthreads();
    if (tid==0) mbar_expect(abE, TXE);
    stasync_v4(raE, rbE, ((const uint4*)estageP)[lane]);
    if (tid<8) stasync_v2(raN, rbN, normloc[0], normloc[1]);
    mbar_wait(abE, par);

    // ======== phase 2: surprise, ee = err @ W1^T, h update ========
    {
      float sA, sB;
      dotp(wsmW, ebufP, row, kq, sA, sB);
      sA += __shfl_down_sync(0xffffffffu, sA, 2, 4);
      sA += __shfl_down_sync(0xffffffffu, sA, 1, 4);
      sB += __shfl_down_sync(0xffffffffu, sB, 2, 4);
      sB += __shfl_down_sync(0xffffffffu, sB, 1, 4);
      if (kq==0) pout2[row] = make_float2(sA, sB);
    }
    __syncthreads();
    if (tid<128){
      float n2 = 0.f;
      #pragma unroll
      for (int s=0;s<CLN;s++) n2 += eb ? narr2[s].y : narr2[s].x;
      float rel = fminf(sqrtf(n2)/xsv, 4.0f);
      float s = sigm((rel - tauv)/gamv);
      float hold = hbufP[eb*HID + rank*64 + erow];
      float eev = eb ? pout2[erow].y : pout2[erow].x;
      float ih = 0.2f*hold + 0.6f*be1v + 0.2f*s*eev;
      float g = s*sa[erow];
      float hn = hold*(1.f-g) + tanhf(ih)*g;
      hstageP[eb*64+erow] = hn;
      g_h1[((b0+eb)*TT+t)*HID + rank*64 + erow] = hn;
    } else if (tid<128+BPC){
      normloc[tid-128]=0.f;                 // reset for next step
    }
    __syncthreads();
    if (tid==0) mbar_expect(abH, TXH);
    stasync_v4(raH, rbH, ((const uint4*)hstageP)[lane]);
    mbar_wait(abH, par);
  }
}

// ---------------- head: out = [h1, be1] @ head_w^T + head_b ----------------
__global__ __launch_bounds__(256) void k_head(const float* __restrict__ hw,
                                              const float* __restrict__ hb,
                                              float* __restrict__ out){
  __shared__ float sh[8*1024];
  __shared__ float sred[4*8*64];
  int tid=threadIdx.x;
  int row0=blockIdx.x*8;
  for (int i=tid;i<8*1024;i+=256){
    int r=i>>10, j=i&1023;
    sh[i] = (j<512)? g_h1[(row0+r)*HID+j] : g_be1[(row0+r)*HID+(j-512)];
  }
  __syncthreads();
  int c=tid&63, q=tid>>6;
  float acc[8];
  #pragma unroll
  for (int r=0;r<8;r++) acc[r]=0.f;
  for (int k=q*256;k<q*256+256;k+=4){
    float4 w = *(const float4*)&hw[c*1024+k];
    #pragma unroll
    for (int r=0;r<8;r++){
      float4 x = *(const float4*)&sh[r*1024+k];
      acc[r] += w.x*x.x + w.y*x.y + w.z*x.z + w.w*x.w;
    }
  }
  #pragma unroll
  for (int r=0;r<8;r++) sred[(q*8+r)*64+c]=acc[r];
  __syncthreads();
  for (int i=tid;i<8*64;i+=256){
    int r=i>>6, cc=i&63;
    out[(row0+r)*NCLS+cc] = sred[r*64+cc] + sred[(8+r)*64+cc]
                          + sred[(16+r)*64+cc] + sred[(24+r)*64+cc] + __ldg(&hb[cc]);
  }
}

// ---------------- launch ----------------
extern "C" void kernel_launch(void* const* d_in, const int* in_sizes, int n_in,
                              void* d_out, int out_size){
  const float* feats=(const float*)d_in[0];
  const float* B0  =(const float*)d_in[2];
  const float* C1  =(const float*)d_in[7];
  const float* B1  =(const float*)d_in[8];
  const float* W1  =(const float*)d_in[9];
  const float* a1  =(const float*)d_in[10];
  const float* tau1=(const float*)d_in[11];
  const float* gam1=(const float*)d_in[12];
  const float* hw  =(const float*)d_in[13];
  const float* hb  =(const float*)d_in[14];
  float* out=(float*)d_out;

  static int smem_set = 0;
  if (!smem_set){
    cudaFuncSetAttribute(k_serial, cudaFuncAttributeMaxDynamicSharedMemorySize, DYNSM);
    smem_set = 1;
  }

  k_be0   <<<NROW/16,256>>>(feats,B0);
  k_be1   <<<NROW/16,256>>>(B1);
  k_serial<<<NCTA,256,DYNSM>>>(C1,W1,a1,tau1,gam1);
  k_head  <<<NROW/8,256>>>(hw,hb,out);
}

// round 10
// speedup vs baseline: 1.2514x; 1.2514x over previous
#include <cuda_runtime.h>
#include <cuda_bf16.h>
#include <math.h>
#include <stdint.h>

#define BQ   16
#define TT   1000
#define MEL  80
#define HID  512
#define NCLS 64
#define NROW (BQ*TT)

#define CLN  8       // CTAs per cluster  (8 clusters x 8 CTAs = 64 -- proven placement)
#define NCTA 64
#define BPC  2       // batch elements per cluster

#define WROWB 1040u                 // bf16 row stride bytes (1024 + 16 pad)
#define WMATB (64u*WROWB)           // 66560 B per matrix slice
#define DYNSM (2u*WMATB)            // 133120 B

// ---------------- scratch (static device globals; no allocations) ----------------
__device__ float g_be0[NROW*HID];
__device__ float g_be1[NROW*HID];
__device__ float g_h1 [NROW*HID];
__device__ float g_xs1[NROW];

__device__ __forceinline__ float sigm(float x){ return 1.0f/(1.0f+expf(-x)); }

__device__ __forceinline__ uint32_t smem_u32(const void* p){
  uint32_t a;
  asm("{ .reg .u64 t; cvta.to.shared.u64 t, %1; cvt.u32.u64 %0, t; }" : "=r"(a) : "l"(p));
  return a;
}
__device__ __forceinline__ void dsmem_st4(uint32_t laddr, uint32_t rnk, float4 v){
  uint32_t ra;
  asm volatile("mapa.shared::cluster.u32 %0, %1, %2;" : "=r"(ra) : "r"(laddr), "r"(rnk));
  asm volatile("st.shared::cluster.v4.f32 [%0], {%1,%2,%3,%4};"
               :: "r"(ra), "f"(v.x), "f"(v.y), "f"(v.z), "f"(v.w) : "memory");
}
__device__ __forceinline__ void dsmem_st1(uint32_t laddr, uint32_t rnk, float v){
  uint32_t ra;
  asm volatile("mapa.shared::cluster.u32 %0, %1, %2;" : "=r"(ra) : "r"(laddr), "r"(rnk));
  asm volatile("st.shared::cluster.f32 [%0], %1;" :: "r"(ra), "f"(v) : "memory");
}
#define CLUSTER_ARRIVE() asm volatile("barrier.cluster.arrive.aligned;" ::: "memory")
#define CLUSTER_WAIT()   asm volatile("barrier.cluster.wait.aligned;"   ::: "memory")

// permuted float4-group position for x buffers: group g (=k/4) -> pos
__host__ __device__ __forceinline__ int xpos(int g){
  int j = g>>1;
  return ((j>>4)<<5) + ((g&1)<<4) + (j&15);
}

// ---------------- be0 = clip(feats/||feats||) @ B0^T ; xs1 = ||be0|| ----------------
__global__ __launch_bounds__(256) void k_be0(const float* __restrict__ feats,
                                             const float* __restrict__ B0){
  __shared__ float xn[16][MEL];
  __shared__ float snorm[16];
  __shared__ float sxs[16];
  int tid = threadIdx.x;
  int row0 = blockIdx.x*16;
  for (int i=tid;i<16*MEL;i+=256)
    xn[i/MEL][i%MEL] = feats[row0*MEL + i];
  __syncthreads();
  if (tid<16){
    float s=0.f;
    #pragma unroll
    for (int k=0;k<MEL;k++){ float v=xn[tid][k]; s+=v*v; }
    sxs[tid]=fmaxf(sqrtf(s),1e-6f);
    snorm[tid]=0.f;
  }
  __syncthreads();
  for (int i=tid;i<16*MEL;i+=256){
    int r=i/MEL;
    float v = xn[r][i%MEL]/sxs[r];
    xn[r][i%MEL] = fminf(fmaxf(v,-1.f),1.f);
  }
  __syncthreads();
  int n0=tid, n1=tid+256;
  float a0[16], a1_[16];
  #pragma unroll
  for (int r=0;r<16;r++){ a0[r]=0.f; a1_[r]=0.f; }
  for (int k=0;k<MEL;k+=4){
    float4 w0 = *(const float4*)&B0[n0*MEL+k];
    float4 w1 = *(const float4*)&B0[n1*MEL+k];
    #pragma unroll
    for (int r=0;r<16;r++){
      float4 x = *(const float4*)&xn[r][k];
      a0 [r] += w0.x*x.x + w0.y*x.y + w0.z*x.z + w0.w*x.w;
      a1_[r] += w1.x*x.x + w1.y*x.y + w1.z*x.z + w1.w*x.w;
    }
  }
  #pragma unroll
  for (int r=0;r<16;r++){
    g_be0[(row0+r)*HID+n0]=a0[r];
    g_be0[(row0+r)*HID+n1]=a1_[r];
    atomicAdd(&snorm[r], a0[r]*a0[r] + a1_[r]*a1_[r]);
  }
  __syncthreads();
  if (tid<16) g_xs1[row0+tid] = fmaxf(sqrtf(snorm[tid]),1e-6f);
}

// ---------------- be1 = clip(be0/xs1) @ B1^T ----------------
__global__ __launch_bounds__(256) void k_be1(const float* __restrict__ B1){
  __shared__ float xn[16][HID];
  __shared__ float sxs[16];
  int tid=threadIdx.x;
  int row0=blockIdx.x*16;
  if (tid<16) sxs[tid]=g_xs1[row0+tid];
  __syncthreads();
  for (int i=tid;i<16*HID;i+=256){
    int r=i>>9;
    float v = g_be0[row0*HID + i]/sxs[r];
    xn[r][i&511] = fminf(fmaxf(v,-1.f),1.f);
  }
  __syncthreads();
  int n0=tid, n1=tid+256;
  float a0[16], a1_[16];
  #pragma unroll
  for (int r=0;r<16;r++){ a0[r]=0.f; a1_[r]=0.f; }
  for (int k=0;k<HID;k+=4){
    float4 w0 = *(const float4*)&B1[n0*HID+k];
    float4 w1 = *(const float4*)&B1[n1*HID+k];
    #pragma unroll
    for (int r=0;r<16;r++){
      float4 x = *(const float4*)&xn[r][k];
      a0 [r] += w0.x*x.x + w0.y*x.y + w0.z*x.z + w0.w*x.w;
      a1_[r] += w1.x*x.x + w1.y*x.y + w1.z*x.z + w1.w*x.w;
    }
  }
  #pragma unroll
  for (int r=0;r<16;r++){
    g_be1[(row0+r)*HID+n0]=a0[r];
    g_be1[(row0+r)*HID+n1]=a1_[r];
  }
}

// ---------------- serial recurrence (R5 structure + latency-hidden waits) ---------
// CTA `rank` owns rows [rank*64, rank*64+64). Weights bf16 in smem; x vectors
// exchanged by DSMEM push in a permuted conflict-free layout; barriers split
// arrive/wait with global-load prefetch inside the wait windows.
__device__ __forceinline__ void dot_bf16(const uint8_t* __restrict__ wsm,
                                         const uint8_t* __restrict__ xb,
                                         int rg, int kq, float* __restrict__ acc){
  const uint8_t* wr = wsm + (unsigned)(rg*4)*WROWB + (unsigned)kq*16u;
  #pragma unroll
  for (int m=0;m<4;m++){
    float4 xa0 = *(const float4*)(xb + (m*32+kq)*16);
    float4 xa1 = *(const float4*)(xb + (m*32+16+kq)*16);
    float4 xb0 = *(const float4*)(xb + 2048 + (m*32+kq)*16);
    float4 xb1 = *(const float4*)(xb + 2048 + (m*32+16+kq)*16);
    #pragma unroll
    for (int r=0;r<4;r++){
      uint4 w = *(const uint4*)(wr + (unsigned)r*WROWB + (unsigned)m*256u);
      float w0=__uint_as_float(w.x<<16), w1=__uint_as_float(w.x&0xffff0000u);
      float w2=__uint_as_float(w.y<<16), w3=__uint_as_float(w.y&0xffff0000u);
      float w4=__uint_as_float(w.z<<16), w5=__uint_as_float(w.z&0xffff0000u);
      float w6=__uint_as_float(w.w<<16), w7=__uint_as_float(w.w&0xffff0000u);
      acc[r*2+0] += w0*xa0.x + w1*xa0.y + w2*xa0.z + w3*xa0.w
                  + w4*xa1.x + w5*xa1.y + w6*xa1.z + w7*xa1.w;
      acc[r*2+1] += w0*xb0.x + w1*xb0.y + w2*xb0.z + w3*xb0.w
                  + w4*xb1.x + w5*xb1.y + w6*xb1.z + w7*xb1.w;
    }
  }
}

__global__ __launch_bounds__(256,1) __cluster_dims__(CLN,1,1)
void k_serial(const float* __restrict__ C1, const float* __restrict__ W1,
              const float* __restrict__ a1, const float* __restrict__ tau,
              const float* __restrict__ gam){
  extern __shared__ __align__(16) uint8_t dynsm[];
  uint8_t* wsmC = dynsm;                 // [64][WROWB] bf16
  uint8_t* wsmW = dynsm + WMATB;

  __shared__ __align__(16) float hbufP[BPC][HID];    // permuted h   (remote-written)
  __shared__ __align__(16) float ebufP[BPC][HID];    // permuted err (remote-written)
  __shared__ __align__(16) float estageP[BPC][64];
  __shared__ __align__(16) float hstageP[BPC][64];
  __shared__ float2 pout2[64];
  __shared__ float narr[BPC][CLN];
  __shared__ float normloc[2][BPC];                  // ping-pong by step parity
  __shared__ float sa[64];

  const int tid  = threadIdx.x;
  const int rank = blockIdx.x & (CLN-1);
  const int b0   = (blockIdx.x / CLN) * BPC;
  const int rg   = tid >> 4, kq = tid & 15;
  const float tauv = __ldg(&tau[0]), gamv = __ldg(&gam[0]);

  // -------- prologue: convert weight slices fp32 -> bf16 smem --------
  for (int i=tid; i<64*128; i+=256){
    int r=i>>7, q=i&127;
    float4 vc = __ldg((const float4*)&C1[(rank*64+r)*HID + q*4]);
    float4 vw = __ldg((const float4*)&W1[(rank*64+r)*HID + q*4]);
    __nv_bfloat162 c0 = __floats2bfloat162_rn(vc.x, vc.y);
    __nv_bfloat162 c1 = __floats2bfloat162_rn(vc.z, vc.w);
    __nv_bfloat162 w0 = __floats2bfloat162_rn(vw.x, vw.y);
    __nv_bfloat162 w1 = __floats2bfloat162_rn(vw.z, vw.w);
    uint2 uc; uc.x = *(uint32_t*)&c0; uc.y = *(uint32_t*)&c1;
    uint2 uw; uw.x = *(uint32_t*)&w0; uw.y = *(uint32_t*)&w1;
    *(uint2*)(wsmC + (unsigned)r*WROWB + (unsigned)q*8u) = uc;
    *(uint2*)(wsmW + (unsigned)r*WROWB + (unsigned)q*8u) = uw;
  }
  for (int i=tid;i<BPC*HID;i+=256) (&hbufP[0][0])[i]=0.f;
  if (tid<2*BPC) (&normloc[0][0])[tid]=0.f;
  if (tid<64)  sa[tid] = sigm(__ldg(&a1[rank*64+tid]));
  __syncthreads();

  const uint32_t a_ebuf = smem_u32(&ebufP[0][0]);
  const uint32_t a_hbuf = smem_u32(&hbufP[0][0]);
  const uint32_t a_narr = smem_u32(&narr[0][0]);

  const int eb = tid & 1, erow = tid >> 1;             // epilogue mapping (tid<128)
  const int dest = tid >> 5, chunk = tid & 31;         // push mapping (256 threads)
  const int pb = chunk >> 4, pq = chunk & 15;
  const uint32_t e_off = (uint32_t)(pb*HID + xpos(rank*16 + pq)*4)*4u;
  const int hk   = rank*64 + erow;
  const int hidx = eb*HID + xpos(hk>>2)*4 + (hk&3);

  // prefetch per-step scalars for t=0
  float xsv=1.f, be0v=0.f, be1v=0.f;
  if (tid<128){
    int bb = b0+eb;
    xsv  = __ldg(&g_xs1[bb*TT]);
    be0v = __ldg(&g_be0[(bb*TT)*HID + rank*64 + erow]);
  }

  for (int t=0;t<TT;t++){
    const int par = t&1;

    // ======== phase 1: p = h @ C1^T (own rows), err, norm partial ========
    {
      float acc[8] = {0.f,0.f,0.f,0.f,0.f,0.f,0.f,0.f};
      dot_bf16(wsmC, (const uint8_t*)&hbufP[0][0], rg, kq, acc);
      #pragma unroll
      for (int off=8; off; off>>=1)
        #pragma unroll
        for (int j=0;j<8;j++) acc[j] += __shfl_down_sync(0xffffffffu, acc[j], off);
      if (kq==0){
        #pragma unroll
        for (int j=0;j<4;j++) pout2[rg*4+j] = make_float2(acc[j*2], acc[j*2+1]);
      }
    }
    __syncthreads();
    if (tid<128){
      float pv = eb ? pout2[erow].y : pout2[erow].x;
      float p = tanhf(pv) * xsv;
      float e = be0v - p;
      estageP[eb][erow] = e;
      float q = e*e;
      #pragma unroll
      for (int off=16; off>=2; off>>=1) q += __shfl_xor_sync(0xffffffffu,q,off);
      if ((tid&31)<2) atomicAdd(&normloc[par][tid&1], q);
    }
    __syncthreads();
    {
      float4 v = ((const float4*)estageP)[chunk];
      dsmem_st4(a_ebuf + e_off, (uint32_t)dest, v);
      if (tid<16)
        dsmem_st1(a_narr + (uint32_t)(((tid&1)*CLN + rank)*4), (uint32_t)(tid>>1),
                  normloc[par][tid&1]);
    }
    CLUSTER_ARRIVE();
    if (tid<128)                    // be1 prefetch hides inside the barrier wait
      be1v = __ldg(&g_be1[((b0+eb)*TT+t)*HID + rank*64 + erow]);
    CLUSTER_WAIT();

    // ======== phase 2: surprise, ee = err @ W1^T, h update ========
    {
      float acc[8] = {0.f,0.f,0.f,0.f,0.f,0.f,0.f,0.f};
      dot_bf16(wsmW, (const uint8_t*)&ebufP[0][0], rg, kq, acc);
      #pragma unroll
      for (int off=8; off; off>>=1)
        #pragma unroll
        for (int j=0;j<8;j++) acc[j] += __shfl_down_sync(0xffffffffu, acc[j], off);
      if (kq==0){
        #pragma unroll
        for (int j=0;j<4;j++) pout2[rg*4+j] = make_float2(acc[j*2], acc[j*2+1]);
      }
    }
    __syncthreads();
    if (tid<128){
      float n2 = (narr[eb][0]+narr[eb][1])+(narr[eb][2]+narr[eb][3])
               + (narr[eb][4]+narr[eb][5])+(narr[eb][6]+narr[eb][7]);
      float rel = fminf(sqrtf(n2)/xsv, 4.0f);
      float s = sigm((rel - tauv)/gamv);
      float hold = hbufP[eb][0] , dummy=0.f; (void)dummy;
      hold = (&hbufP[0][0])[hidx];
      float eev = eb ? pout2[erow].y : pout2[erow].x;
      float ih = 0.2f*hold + 0.6f*be1v + 0.2f*s*eev;
      float g = s*sa[erow];
      float hn = hold*(1.f-g) + tanhf(ih)*g;
      hstageP[eb][erow] = hn;
      g_h1[((b0+eb)*TT+t)*HID + rank*64 + erow] = hn;
      if (tid<2) normloc[par^1][tid] = 0.f;            // reset other slot
    }
    __syncthreads();
    {
      float4 v = ((const float4*)hstageP)[chunk];
      dsmem_st4(a_hbuf + e_off, (uint32_t)dest, v);
    }
    CLUSTER_ARRIVE();
    if (tid<128 && t+1<TT){         // next-step scalars hide inside the wait
      int bb = b0+eb;
      xsv  = __ldg(&g_xs1[bb*TT+t+1]);
      be0v = __ldg(&g_be0[(bb*TT+t+1)*HID + rank*64 + erow]);
    }
    CLUSTER_WAIT();
  }
}

// ---------------- head: out = [h1, be1] @ head_w^T + head_b ----------------
__global__ __launch_bounds__(256) void k_head(const float* __restrict__ hw,
                                              const float* __restrict__ hb,
                                              float* __restrict__ out){
  __shared__ float sh[8*1024];
  __shared__ float sred[4*8*64];
  int tid=threadIdx.x;
  int row0=blockIdx.x*8;
  for (int i=tid;i<8*1024;i+=256){
    int r=i>>10, j=i&1023;
    sh[i] = (j<512)? g_h1[(row0+r)*HID+j] : g_be1[(row0+r)*HID+(j-512)];
  }
  __syncthreads();
  int c=tid&63, q=tid>>6;
  float acc[8];
  #pragma unroll
  for (int r=0;r<8;r++) acc[r]=0.f;
  for (int k=q*256;k<q*256+256;k+=4){
    float4 w = *(const float4*)&hw[c*1024+k];
    #pragma unroll
    for (int r=0;r<8;r++){
      float4 x = *(const float4*)&sh[r*1024+k];
      acc[r] += w.x*x.x + w.y*x.y + w.z*x.z + w.w*x.w;
    }
  }
  #pragma unroll
  for (int r=0;r<8;r++) sred[(q*8+r)*64+c]=acc[r];
  __syncthreads();
  for (int i=tid;i<8*64;i+=256){
    int r=i>>6, cc=i&63;
    out[(row0+r)*NCLS+cc] = sred[r*64+cc] + sred[(8+r)*64+cc]
                          + sred[(16+r)*64+cc] + sred[(24+r)*64+cc] + __ldg(&hb[cc]);
  }
}

// ---------------- launch ----------------
extern "C" void kernel_launch(void* const* d_in, const int* in_sizes, int n_in,
                              void* d_out, int out_size){
  const float* feats=(const float*)d_in[0];
  const float* B0  =(const float*)d_in[2];
  const float* C1  =(const float*)d_in[7];
  const float* B1  =(const float*)d_in[8];
  const float* W1  =(const float*)d_in[9];
  const float* a1  =(const float*)d_in[10];
  const float* tau1=(const float*)d_in[11];
  const float* gam1=(const float*)d_in[12];
  const float* hw  =(const float*)d_in[13];
  const float* hb  =(const float*)d_in[14];
  float* out=(float*)d_out;

  static int smem_set = 0;
  if (!smem_set){
    cudaFuncSetAttribute(k_serial, cudaFuncAttributeMaxDynamicSharedMemorySize, DYNSM);
    smem_set = 1;
  }

  k_be0   <<<NROW/16,256>>>(feats,B0);
  k_be1   <<<NROW/16,256>>>(B1);
  k_serial<<<NCTA,256,DYNSM>>>(C1,W1,a1,tau1,gam1);
  k_head  <<<NROW/8,256>>>(hw,hb,out);
}